// round 4
// baseline (speedup 1.0000x reference)
#include <cuda_runtime.h>

// LengthRegulator: out[b, t, :] = x[b, j, :] where token j owns frame t,
// i.e. cum[b][j-1] <= t < cum[b][j]; zero for t >= cum[b][L-1].
// Second output: durations echoed back as float.
// Shapes: N=16, L=512, D=384, T=3584.
//
// Two launches:
//   1. lr_prep_kernel  : per-batch scan + frame->token scatter + echo (fused)
//   2. lr_expand_kernel: the 88 MB gather/store stream (bandwidth-bound)

#define NB 16
#define LL 512
#define DD 384
#define V4 (DD / 4)                      // 96 float4 per frame
#define FRAMES_PER_BLK 8
#define THREADS (V4 * FRAMES_PER_BLK)    // 768

// Scratch (allocation-free rule: __device__ globals).
__device__ int g_cum[NB * LL];           // inclusive cumsum of durations
__device__ int g_idx[NB * 4096];         // frame -> token map (T <= 4096)

// ---------------------------------------------------------------------------
// Kernel 1: fused prep. 16 blocks x 512 threads (one thread per token).
//  a) inclusive block scan of durations (warp shfl + cross-warp combine)
//  b) scatter token id into g_idx over its owned frame range
//  c) echo duration as float into the tail of d_out
// ---------------------------------------------------------------------------
__global__ void lr_prep_kernel(const int* __restrict__ dur,
                               float* __restrict__ echo_dst) {
    __shared__ int warp_sums[16];        // 512/32 = 16 warps
    const int b = blockIdx.x;
    const int j = threadIdx.x;           // token index 0..511
    const int lane = j & 31;
    const int w = j >> 5;

    const int d = dur[b * LL + j];

    // inclusive warp scan
    int inc = d;
#pragma unroll
    for (int off = 1; off < 32; off <<= 1) {
        int v = __shfl_up_sync(0xffffffffu, inc, off);
        if (lane >= off) inc += v;
    }
    if (lane == 31) warp_sums[w] = inc;
    __syncthreads();

    // scan of warp sums by warp 0
    if (w == 0) {
        int s = warp_sums[lane & 15];
#pragma unroll
        for (int off = 1; off < 16; off <<= 1) {
            int v = __shfl_up_sync(0xffffffffu, s, off);
            if ((lane & 15) >= off) s += v;
        }
        if (lane < 16) warp_sums[lane] = s;
    }
    __syncthreads();

    const int c = inc + (w > 0 ? warp_sums[w - 1] : 0);   // inclusive cumsum
    g_cum[b * LL + j] = c;

    // scatter: frames [c-d, c) belong to token j (d <= 7)
    int* row = g_idx + b * 4096;
    const int start = c - d;
    for (int k = 0; k < d; ++k)
        row[start + k] = j;

    // echo durations as float
    if (echo_dst) echo_dst[b * LL + j] = (float)d;
}

// ---------------------------------------------------------------------------
// Kernel 2: expand. grid = (T/8, N), block = 768 threads.
// 96 lanes (3 full warps) per frame: broadcast token-id load, float4 gather
// from x (L2-resident, 12.6 MB), coalesced float4 store (88 MB total).
// ---------------------------------------------------------------------------
__global__ void __launch_bounds__(THREADS)
lr_expand_kernel(const float* __restrict__ x,
                 float* __restrict__ out, int T) {
    const int b = blockIdx.y;
    const int tid = threadIdx.x;
    const int f = tid / V4;              // 0..7
    const int v = tid % V4;              // 0..95
    const int t = blockIdx.x * FRAMES_PER_BLK + f;

    const int total = __ldg(&g_cum[b * LL + (LL - 1)]);

    float4 val = make_float4(0.f, 0.f, 0.f, 0.f);
    if (t < total) {
        const int j = __ldg(&g_idx[b * 4096 + t]);    // warp-uniform
        val = reinterpret_cast<const float4*>(
                  x + ((size_t)b * LL + j) * DD)[v];
    }
    reinterpret_cast<float4*>(out + ((size_t)b * T + t) * DD)[v] = val;
}

extern "C" void kernel_launch(void* const* d_in, const int* in_sizes, int n_in,
                              void* d_out, int out_size) {
    const float* x = (const float*)d_in[0];
    const int* dur = (const int*)d_in[1];

    const int NL = NB * LL;                          // 8192
    const long long per_frame = (long long)NB * DD;  // 6144 elems per time step

    long long main_elems = out_size;
    float* echo_dst = nullptr;
    if (main_elems % per_frame != 0) {
        main_elems -= NL;
        echo_dst = (float*)d_out + main_elems;
    }
    const int T = (int)(main_elems / per_frame);     // 3584

    lr_prep_kernel<<<NB, LL>>>(dur, echo_dst);

    dim3 grid(T / FRAMES_PER_BLK, NB);
    lr_expand_kernel<<<grid, THREADS>>>(x, (float*)d_out, T);
}

// round 5
// speedup vs baseline: 1.3819x; 1.3819x over previous
#include <cuda_runtime.h>

// LengthRegulator: out[b, t, :] = x[b, j, :] where token j owns frame t,
// i.e. cum[b][j-1] <= t < cum[b][j]; zero for t >= cum[b][L-1].
// Second output: durations echoed back as float.
// Shapes: N=16, L=512, D=384, T=3584.

#define NB 16
#define LL 512
#define DD 384
#define V4 (DD / 4)                      // 96 float4 per frame
#define GROUPS 8                         // frame-groups per block
#define FPT 4                            // frames per thread (ILP)
#define TILE (GROUPS * FPT)              // 32 frames per block
#define THREADS (V4 * GROUPS)            // 768

// Scratch (allocation-free rule: __device__ globals).
__device__ int g_cum[NB * LL];           // inclusive cumsum of durations
__device__ int g_idx[NB * 4096];         // frame -> token map (T <= 4096)

// ---------------------------------------------------------------------------
// Kernel 1: fused prep. 16 blocks x 512 threads (one thread per token).
//  a) inclusive block scan of durations
//  b) scatter token id into g_idx over its owned frame range
//  c) echo duration as float into the tail of d_out
// ---------------------------------------------------------------------------
__global__ void lr_prep_kernel(const int* __restrict__ dur,
                               float* __restrict__ echo_dst) {
    __shared__ int warp_sums[16];
    const int b = blockIdx.x;
    const int j = threadIdx.x;
    const int lane = j & 31;
    const int w = j >> 5;

    const int d = dur[b * LL + j];

    int inc = d;
#pragma unroll
    for (int off = 1; off < 32; off <<= 1) {
        int v = __shfl_up_sync(0xffffffffu, inc, off);
        if (lane >= off) inc += v;
    }
    if (lane == 31) warp_sums[w] = inc;
    __syncthreads();

    if (w == 0) {
        int s = warp_sums[lane & 15];
#pragma unroll
        for (int off = 1; off < 16; off <<= 1) {
            int v = __shfl_up_sync(0xffffffffu, s, off);
            if ((lane & 15) >= off) s += v;
        }
        if (lane < 16) warp_sums[lane] = s;
    }
    __syncthreads();

    const int c = inc + (w > 0 ? warp_sums[w - 1] : 0);
    g_cum[b * LL + j] = c;

    int* row = g_idx + b * 4096;
    const int start = c - d;
    for (int k = 0; k < d; ++k)
        row[start + k] = j;

    if (echo_dst) echo_dst[b * LL + j] = (float)d;
}

// ---------------------------------------------------------------------------
// Kernel 2: expand with 4-frame ILP.
// grid = (T/32, N), block = 768. Group f (96 lanes) handles frames
// tb+4f .. tb+4f+3: one int4 load of 4 token ids, 4 independent float4
// gathers, 4 coalesced float4 stores.
// ---------------------------------------------------------------------------
__global__ void __launch_bounds__(THREADS)
lr_expand_kernel(const float* __restrict__ x,
                 float* __restrict__ out, int T) {
    const int b = blockIdx.y;
    const int tid = threadIdx.x;
    const int f = tid / V4;              // 0..7
    const int v = tid % V4;              // 0..95
    const int t0 = blockIdx.x * TILE + f * FPT;   // first of 4 consecutive frames

    const int total = __ldg(&g_cum[b * LL + (LL - 1)]);

    // 4 consecutive token ids in one 128-bit load (warp-uniform address).
    const int4 jj = *reinterpret_cast<const int4*>(&g_idx[b * 4096 + t0]);
    const int js[FPT] = {jj.x, jj.y, jj.z, jj.w};

    const float4* xb = reinterpret_cast<const float4*>(x + (size_t)b * LL * DD);

    float4 val[FPT];
#pragma unroll
    for (int k = 0; k < FPT; ++k) {
        val[k] = make_float4(0.f, 0.f, 0.f, 0.f);
        if (t0 + k < total)
            val[k] = xb[(size_t)js[k] * V4 + v];   // 4 independent gathers
    }

    float4* ob = reinterpret_cast<float4*>(out + ((size_t)b * T + t0) * DD);
#pragma unroll
    for (int k = 0; k < FPT; ++k)
        ob[(size_t)k * V4 + v] = val[k];
}

extern "C" void kernel_launch(void* const* d_in, const int* in_sizes, int n_in,
                              void* d_out, int out_size) {
    const float* x = (const float*)d_in[0];
    const int* dur = (const int*)d_in[1];

    const int NL = NB * LL;                          // 8192
    const long long per_frame = (long long)NB * DD;  // 6144 elems per time step

    long long main_elems = out_size;
    float* echo_dst = nullptr;
    if (main_elems % per_frame != 0) {
        main_elems -= NL;
        echo_dst = (float*)d_out + main_elems;
    }
    const int T = (int)(main_elems / per_frame);     // 3584

    lr_prep_kernel<<<NB, LL>>>(dur, echo_dst);

    dim3 grid(T / TILE, NB);                         // 112 x 16 = 1792 blocks
    lr_expand_kernel<<<grid, THREADS>>>(x, (float*)d_out, T);
}

// round 6
// speedup vs baseline: 1.7215x; 1.2457x over previous
#include <cuda_runtime.h>

// LengthRegulator: out[b, t, :] = x[b, j, :] where token j owns frame t,
// i.e. cum[b][j-1] <= t < cum[b][j]; zero for t >= cum[b][L-1].
// Second output: durations echoed back as float.
// Shapes: N=16, L=512, D=384, T=3584.

#define NB 16
#define LL 512
#define DD 384
#define V4 (DD / 4)                      // 96 float4 per frame
#define GROUPS 4                         // frame-groups per block
#define FPT 8                            // frames per thread (ILP/MLP)
#define TILE (GROUPS * FPT)              // 32 frames per block
#define THREADS (V4 * GROUPS)            // 384

// Scratch (allocation-free rule: __device__ globals).
__device__ int g_cum[NB * LL];           // inclusive cumsum of durations
__device__ int g_idx[NB * 4096];         // frame -> token map (T <= 4096)

// ---------------------------------------------------------------------------
// Kernel 1: fused prep. 16 blocks x 512 threads (one thread per token).
// ---------------------------------------------------------------------------
__global__ void lr_prep_kernel(const int* __restrict__ dur,
                               float* __restrict__ echo_dst) {
    __shared__ int warp_sums[16];
    const int b = blockIdx.x;
    const int j = threadIdx.x;
    const int lane = j & 31;
    const int w = j >> 5;

    const int d = dur[b * LL + j];

    int inc = d;
#pragma unroll
    for (int off = 1; off < 32; off <<= 1) {
        int v = __shfl_up_sync(0xffffffffu, inc, off);
        if (lane >= off) inc += v;
    }
    if (lane == 31) warp_sums[w] = inc;
    __syncthreads();

    if (w == 0) {
        int s = warp_sums[lane & 15];
#pragma unroll
        for (int off = 1; off < 16; off <<= 1) {
            int v = __shfl_up_sync(0xffffffffu, s, off);
            if ((lane & 15) >= off) s += v;
        }
        if (lane < 16) warp_sums[lane] = s;
    }
    __syncthreads();

    const int c = inc + (w > 0 ? warp_sums[w - 1] : 0);
    g_cum[b * LL + j] = c;

    int* row = g_idx + b * 4096;
    const int start = c - d;
    for (int k = 0; k < d; ++k)
        row[start + k] = j;

    if (echo_dst) echo_dst[b * LL + j] = (float)d;
}

// ---------------------------------------------------------------------------
// Kernel 2: expand with 8-frame ILP.
// grid = (T/32, N), block = 384. Group f (96 lanes) handles frames
// tb+8f .. tb+8f+7: two int4 loads of token ids, 8 independent float4
// gathers, 8 coalesced streaming float4 stores.
// ---------------------------------------------------------------------------
__global__ void __launch_bounds__(THREADS)
lr_expand_kernel(const float* __restrict__ x,
                 float* __restrict__ out, int T) {
    const int b = blockIdx.y;
    const int tid = threadIdx.x;
    const int f = tid / V4;              // 0..3
    const int v = tid % V4;              // 0..95
    const int t0 = blockIdx.x * TILE + f * FPT;   // first of 8 consecutive frames

    const int total = __ldg(&g_cum[b * LL + (LL - 1)]);

    // 8 consecutive token ids via two 128-bit loads (warp-uniform addresses).
    const int4* jp = reinterpret_cast<const int4*>(&g_idx[b * 4096 + t0]);
    const int4 j0 = jp[0];
    const int4 j1 = jp[1];
    const int js[FPT] = {j0.x, j0.y, j0.z, j0.w, j1.x, j1.y, j1.z, j1.w};

    const float4* xb = reinterpret_cast<const float4*>(x + (size_t)b * LL * DD);

    float4 val[FPT];
#pragma unroll
    for (int k = 0; k < FPT; ++k) {
        val[k] = make_float4(0.f, 0.f, 0.f, 0.f);
        if (t0 + k < total)
            val[k] = xb[(size_t)js[k] * V4 + v];   // 8 independent gathers
    }

    float4* ob = reinterpret_cast<float4*>(out + ((size_t)b * T + t0) * DD);
#pragma unroll
    for (int k = 0; k < FPT; ++k)
        __stcs(&ob[(size_t)k * V4 + v], val[k]);   // streaming: evict-first
}

extern "C" void kernel_launch(void* const* d_in, const int* in_sizes, int n_in,
                              void* d_out, int out_size) {
    const float* x = (const float*)d_in[0];
    const int* dur = (const int*)d_in[1];

    const int NL = NB * LL;                          // 8192
    const long long per_frame = (long long)NB * DD;  // 6144 elems per time step

    long long main_elems = out_size;
    float* echo_dst = nullptr;
    if (main_elems % per_frame != 0) {
        main_elems -= NL;
        echo_dst = (float*)d_out + main_elems;
    }
    const int T = (int)(main_elems / per_frame);     // 3584

    lr_prep_kernel<<<NB, LL>>>(dur, echo_dst);

    dim3 grid(T / TILE, NB);                         // 112 x 16 = 1792 blocks
    lr_expand_kernel<<<grid, THREADS>>>(x, (float*)d_out, T);
}